// round 1
// baseline (speedup 1.0000x reference)
#include <cuda_runtime.h>
#include <cuda_bf16.h>
#include <cuda_fp16.h>
#include <cstdint>

#define BB 4
#define SS 4096
#define DD 512
#define BSD (BB*SS*DD)      // 8388608
// E matrix: BB*SS*SS = 67108864 elements (fp16, 128MB)

// ---------------- device scratch (static; no allocations allowed) -------------
__device__ __nv_bfloat16 g_xhi[BSD];
__device__ __nv_bfloat16 g_xlo[BSD];
__device__ __nv_bfloat16 g_K[BSD];
__device__ __nv_bfloat16 g_Q[BSD];
__device__ float         g_V[BSD];
__device__ __half        g_E[(size_t)BB*SS*SS];
__device__ float         g_rc[BB*SS];   // 1/colsum
__device__ float         g_rs[BB*SS];   // rowsum
__device__ __nv_bfloat16 g_Wk[DD*DD], g_Wq[DD*DD];
__device__ __nv_bfloat16 g_Wvhi[DD*DD], g_Wvlo[DD*DD];
__device__ __nv_bfloat16 g_Wlhi[DD*DD], g_Wllo[DD*DD];
__device__ __nv_bfloat16 g_ahi[BSD], g_alo[BSD];

// ---------------- helpers ----------------------------------------------------
__device__ __forceinline__ unsigned sptr(const void* p){
    return (unsigned)__cvta_generic_to_shared(p);
}
__device__ __forceinline__ void ldm4(unsigned r[4], unsigned addr){
    asm volatile("ldmatrix.sync.aligned.m8n8.x4.shared.b16 {%0,%1,%2,%3}, [%4];"
        : "=r"(r[0]),"=r"(r[1]),"=r"(r[2]),"=r"(r[3]) : "r"(addr));
}
__device__ __forceinline__ void mma16816(float c[4], const unsigned a[4], const unsigned b[2]){
    asm volatile("mma.sync.aligned.m16n8k16.row.col.f32.bf16.bf16.f32 "
        "{%0,%1,%2,%3},{%4,%5,%6,%7},{%8,%9},{%0,%1,%2,%3};"
        : "+f"(c[0]),"+f"(c[1]),"+f"(c[2]),"+f"(c[3])
        : "r"(a[0]),"r"(a[1]),"r"(a[2]),"r"(a[3]),"r"(b[0]),"r"(b[1]));
}

// ---------------- prep: bf16 conversions + hi/lo splits -----------------------
__global__ void prep_kernel(const float* __restrict__ xs, const float* __restrict__ Wk,
                            const float* __restrict__ Wq, const float* __restrict__ Wv,
                            const float* __restrict__ Wl){
    long i = (long)blockIdx.x*blockDim.x + threadIdx.x;
    if (i < (long)BSD){
        float v = xs[i];
        __nv_bfloat16 h = __float2bfloat16(v);
        g_xhi[i] = h;
        g_xlo[i] = __float2bfloat16(v - __bfloat162float(h));
    }
    if (i < DD*DD){
        g_Wk[i] = __float2bfloat16(Wk[i]);
        g_Wq[i] = __float2bfloat16(Wq[i]);
        float wv = Wv[i]; __nv_bfloat16 vh = __float2bfloat16(wv);
        g_Wvhi[i] = vh; g_Wvlo[i] = __float2bfloat16(wv - __bfloat162float(vh));
        float wl = Wl[i]; __nv_bfloat16 lh = __float2bfloat16(wl);
        g_Wlhi[i] = lh; g_Wllo[i] = __float2bfloat16(wl - __bfloat162float(lh));
    }
}

// ---------------- generic C = A * B^T GEMM on mma.sync bf16 -------------------
// A: [M,Kd] row-major bf16, B: [N,Kd] row-major bf16 (so C = A*B^T), fp32 accum.
// EPI: 0 = bf16 store (+bias)   (K,Q projections)
//      1 = fp32 store (+bias)   (V projection)
//      2 = exp(acc/512) -> fp16 store (QK)
//      3 = tanh(acc+bias) -> fp32 store (output projection)
// SPLIT: A2/B2 are lo parts; accumulate Ahi*Bhi + Ahi*Blo + Alo*Bhi.
constexpr int Bb_M = 128, Bb_N = 128, Bb_K = 32, LDS = 40; // 40-half padded rows

template<int EPI, bool SPLIT>
__global__ void __launch_bounds__(256)
gemm_kernel(const __nv_bfloat16* __restrict__ A, const __nv_bfloat16* __restrict__ A2,
            const __nv_bfloat16* __restrict__ B, const __nv_bfloat16* __restrict__ B2,
            const float* __restrict__ bias, void* __restrict__ Cout,
            int N, int Kd, long batchA, long batchB, long batchC)
{
    extern __shared__ __nv_bfloat16 sm[];
    __nv_bfloat16* As  = sm;
    __nv_bfloat16* Bs  = sm +   Bb_M*LDS;
    __nv_bfloat16* As2 = sm + 2*Bb_M*LDS;
    __nv_bfloat16* Bs2 = sm + 3*Bb_M*LDS;

    int z = blockIdx.z;
    const __nv_bfloat16* Ag  = A  + z*batchA;
    const __nv_bfloat16* Bg  = B  + z*batchB;
    const __nv_bfloat16* A2g = SPLIT ? A2 + z*batchA : nullptr;
    const __nv_bfloat16* B2g = SPLIT ? B2 + z*batchB : nullptr;

    int tid = threadIdx.x, lane = tid & 31, warp = tid >> 5;
    int wm = warp >> 2, wn = warp & 3;           // 2x4 warp grid -> 64x32 per warp
    int bm0 = blockIdx.y * Bb_M, bn0 = blockIdx.x * Bb_N;

    int lr = tid >> 1;                            // loader row 0..127
    int lc = (tid & 1) * 8;                       // loader col (halfs)

    float acc[4][4][4];
    #pragma unroll
    for (int i=0;i<4;i++)
        #pragma unroll
        for (int j=0;j<4;j++)
            #pragma unroll
            for (int k=0;k<4;k++) acc[i][j][k]=0.f;

    for (int k0 = 0; k0 < Kd; k0 += Bb_K){
        {
            const __nv_bfloat16* s = Ag + (long)(bm0+lr)*Kd + k0 + lc;
            *(uint4*)(As + lr*LDS + lc)      = *(const uint4*)(s);
            *(uint4*)(As + lr*LDS + lc + 16) = *(const uint4*)(s + 16);
            const __nv_bfloat16* t = Bg + (long)(bn0+lr)*Kd + k0 + lc;
            *(uint4*)(Bs + lr*LDS + lc)      = *(const uint4*)(t);
            *(uint4*)(Bs + lr*LDS + lc + 16) = *(const uint4*)(t + 16);
            if (SPLIT){
                const __nv_bfloat16* s2 = A2g + (long)(bm0+lr)*Kd + k0 + lc;
                *(uint4*)(As2 + lr*LDS + lc)      = *(const uint4*)(s2);
                *(uint4*)(As2 + lr*LDS + lc + 16) = *(const uint4*)(s2 + 16);
                const __nv_bfloat16* t2 = B2g + (long)(bn0+lr)*Kd + k0 + lc;
                *(uint4*)(Bs2 + lr*LDS + lc)      = *(const uint4*)(t2);
                *(uint4*)(Bs2 + lr*LDS + lc + 16) = *(const uint4*)(t2 + 16);
            }
        }
        __syncthreads();

        #pragma unroll
        for (int kk = 0; kk < Bb_K; kk += 16){
            unsigned af[4][4], bf[4][2];
            unsigned af2[4][4], bf2[4][2];
            int arow = wm*64 + (lane & 15);
            int acol = kk + 8*(lane >> 4);
            #pragma unroll
            for (int mi=0; mi<4; mi++){
                ldm4(af[mi],  sptr(As  + (arow + mi*16)*LDS + acol));
                if (SPLIT) ldm4(af2[mi], sptr(As2 + (arow + mi*16)*LDS + acol));
            }
            int brow = wn*32 + (lane & 7) + ((lane & 16) ? 8 : 0);
            int bcol = kk + ((lane & 8) ? 8 : 0);
            #pragma unroll
            for (int nb=0; nb<2; nb++){
                unsigned tmp[4];
                ldm4(tmp, sptr(Bs + (brow + nb*16)*LDS + bcol));
                bf[2*nb][0]=tmp[0]; bf[2*nb][1]=tmp[1];
                bf[2*nb+1][0]=tmp[2]; bf[2*nb+1][1]=tmp[3];
                if (SPLIT){
                    ldm4(tmp, sptr(Bs2 + (brow + nb*16)*LDS + bcol));
                    bf2[2*nb][0]=tmp[0]; bf2[2*nb][1]=tmp[1];
                    bf2[2*nb+1][0]=tmp[2]; bf2[2*nb+1][1]=tmp[3];
                }
            }
            #pragma unroll
            for (int mi=0; mi<4; mi++)
                #pragma unroll
                for (int ni=0; ni<4; ni++){
                    mma16816(acc[mi][ni], af[mi], bf[ni]);
                    if (SPLIT){
                        mma16816(acc[mi][ni], af[mi],  bf2[ni]);
                        mma16816(acc[mi][ni], af2[mi], bf[ni]);
                    }
                }
        }
        __syncthreads();
    }

    // epilogue
    int tr = lane >> 2, tc = (lane & 3) * 2;
    #pragma unroll
    for (int mi=0; mi<4; mi++){
        #pragma unroll
        for (int ni=0; ni<4; ni++){
            int row = bm0 + wm*64 + mi*16 + tr;
            int col = bn0 + wn*32 + ni*8 + tc;
            float* a = acc[mi][ni];
            if (EPI == 0){
                __nv_bfloat16* C = (__nv_bfloat16*)Cout;
                float b0 = bias[col], b1 = bias[col+1];
                *(__nv_bfloat162*)(C + (long)row*N + col)     = __floats2bfloat162_rn(a[0]+b0, a[1]+b1);
                *(__nv_bfloat162*)(C + (long)(row+8)*N + col) = __floats2bfloat162_rn(a[2]+b0, a[3]+b1);
            } else if (EPI == 1){
                float* C = (float*)Cout;
                float b0 = bias[col], b1 = bias[col+1];
                *(float2*)(C + (long)row*N + col)     = make_float2(a[0]+b0, a[1]+b1);
                *(float2*)(C + (long)(row+8)*N + col) = make_float2(a[2]+b0, a[3]+b1);
            } else if (EPI == 2){
                __half* C = (__half*)Cout + z*batchC;
                const float inv = 1.0f/512.0f;
                *(__half2*)(C + (long)row*N + col)     = __floats2half2_rn(__expf(a[0]*inv), __expf(a[1]*inv));
                *(__half2*)(C + (long)(row+8)*N + col) = __floats2half2_rn(__expf(a[2]*inv), __expf(a[3]*inv));
            } else {
                float* C = (float*)Cout;
                float b0 = bias[col], b1 = bias[col+1];
                *(float2*)(C + (long)row*N + col)     = make_float2(tanhf(a[0]+b0), tanhf(a[1]+b1));
                *(float2*)(C + (long)(row+8)*N + col) = make_float2(tanhf(a[2]+b0), tanhf(a[3]+b1));
            }
        }
    }
}

// ---------------- colsum: rc[b,e] = 1 / sum_s E[b,s,e]  (deterministic) ------
__global__ void __launch_bounds__(256) colsum_kernel(){
    __shared__ float red[256];
    int b = blockIdx.y;
    int e = blockIdx.x*64 + (threadIdx.x & 63);
    int g = threadIdx.x >> 6;
    const __half* E = g_E + (long)b*SS*SS;
    float s = 0.f;
    for (int r = g; r < SS; r += 4) s += __half2float(E[(long)r*SS + e]);
    red[threadIdx.x] = s;
    __syncthreads();
    if (g == 0){
        int t = threadIdx.x;
        g_rc[b*SS + e] = 1.0f/(red[t] + red[t+64] + red[t+128] + red[t+192]);
    }
}

// ---------------- rowsum: rs[b,s] = sum_e E[b,s,e] * rc[b,e] ------------------
__global__ void __launch_bounds__(256) rowsum_kernel(){
    __shared__ float rcs[SS];
    int b = blockIdx.y;
    for (int i = threadIdx.x; i < SS; i += 256) rcs[i] = g_rc[b*SS + i];
    __syncthreads();
    int lane = threadIdx.x & 31, warp = threadIdx.x >> 5;
    int r0 = blockIdx.x*64 + warp*8;
    for (int k = 0; k < 8; k++){
        int r = r0 + k;
        const __half2* row = (const __half2*)(g_E + ((long)b*SS + r)*(long)SS);
        float s = 0.f;
        for (int j = lane; j < SS/2; j += 32){
            float2 f = __half22float2(row[j]);
            s += f.x*rcs[2*j] + f.y*rcs[2*j+1];
        }
        #pragma unroll
        for (int o = 16; o; o >>= 1) s += __shfl_xor_sync(0xffffffffu, s, o);
        if (lane == 0) g_rs[b*SS + r] = s;
    }
}

// ---------------- attn = rowsum * V  ->  hi/lo bf16 split ---------------------
__global__ void __launch_bounds__(256) attn_kernel(){
    long i = ((long)blockIdx.x*blockDim.x + threadIdx.x)*4;
    if (i >= (long)BSD) return;
    float rs = g_rs[i/DD];
    float4 v = *(const float4*)(g_V + i);
    float a0 = rs*v.x, a1 = rs*v.y, a2 = rs*v.z, a3 = rs*v.w;
    __nv_bfloat16 h0=__float2bfloat16(a0), h1=__float2bfloat16(a1),
                  h2=__float2bfloat16(a2), h3=__float2bfloat16(a3);
    __nv_bfloat162 p0; p0.x=h0; p0.y=h1;
    __nv_bfloat162 p1; p1.x=h2; p1.y=h3;
    *(__nv_bfloat162*)(g_ahi + i)     = p0;
    *(__nv_bfloat162*)(g_ahi + i + 2) = p1;
    __nv_bfloat162 q0, q1;
    q0.x = __float2bfloat16(a0 - __bfloat162float(h0));
    q0.y = __float2bfloat16(a1 - __bfloat162float(h1));
    q1.x = __float2bfloat16(a2 - __bfloat162float(h2));
    q1.y = __float2bfloat16(a3 - __bfloat162float(h3));
    *(__nv_bfloat162*)(g_alo + i)     = q0;
    *(__nv_bfloat162*)(g_alo + i + 2) = q1;
}

// ---------------- launch -----------------------------------------------------
extern "C" void kernel_launch(void* const* d_in, const int* in_sizes, int n_in,
                              void* d_out, int out_size)
{
    const float* xs = (const float*)d_in[0];
    const float* Wk = (const float*)d_in[1]; const float* bk = (const float*)d_in[2];
    const float* Wq = (const float*)d_in[3]; const float* bq = (const float*)d_in[4];
    const float* Wv = (const float*)d_in[5]; const float* bv = (const float*)d_in[6];
    const float* Wl = (const float*)d_in[7]; const float* bl = (const float*)d_in[8];

    void *p_xhi,*p_xlo,*p_K,*p_Q,*p_V,*p_E,*p_ahi,*p_alo;
    void *p_Wk,*p_Wq,*p_Wvhi,*p_Wvlo,*p_Wlhi,*p_Wllo;
    cudaGetSymbolAddress(&p_xhi, g_xhi);   cudaGetSymbolAddress(&p_xlo, g_xlo);
    cudaGetSymbolAddress(&p_K,   g_K);     cudaGetSymbolAddress(&p_Q,   g_Q);
    cudaGetSymbolAddress(&p_V,   g_V);     cudaGetSymbolAddress(&p_E,   g_E);
    cudaGetSymbolAddress(&p_ahi, g_ahi);   cudaGetSymbolAddress(&p_alo, g_alo);
    cudaGetSymbolAddress(&p_Wk,  g_Wk);    cudaGetSymbolAddress(&p_Wq,  g_Wq);
    cudaGetSymbolAddress(&p_Wvhi,g_Wvhi);  cudaGetSymbolAddress(&p_Wvlo,g_Wvlo);
    cudaGetSymbolAddress(&p_Wlhi,g_Wlhi);  cudaGetSymbolAddress(&p_Wllo,g_Wllo);

    const size_t smem1 = 2*Bb_M*LDS*sizeof(__nv_bfloat16);   // 20480
    const size_t smem2 = 4*Bb_M*LDS*sizeof(__nv_bfloat16);   // 40960

    // 1. prep (x splits + weight conversions)
    prep_kernel<<<(BSD + 255)/256, 256>>>(xs, Wk, Wq, Wv, Wl);

    // 2. K, Q projections (plain bf16) and V projection (split)
    dim3 gp(DD/Bb_N, (BB*SS)/Bb_M, 1);   // (4, 128)
    gemm_kernel<0,false><<<gp, 256, smem1>>>(
        (const __nv_bfloat16*)p_xhi, nullptr, (const __nv_bfloat16*)p_Wk, nullptr,
        bk, p_K, DD, DD, 0, 0, 0);
    gemm_kernel<0,false><<<gp, 256, smem1>>>(
        (const __nv_bfloat16*)p_xhi, nullptr, (const __nv_bfloat16*)p_Wq, nullptr,
        bq, p_Q, DD, DD, 0, 0, 0);
    gemm_kernel<1,true><<<gp, 256, smem2>>>(
        (const __nv_bfloat16*)p_xhi, (const __nv_bfloat16*)p_xlo,
        (const __nv_bfloat16*)p_Wvhi, (const __nv_bfloat16*)p_Wvlo,
        bv, p_V, DD, DD, 0, 0, 0);

    // 3. E = exp(K Q^T / 512), fp16, per batch
    dim3 gq(SS/Bb_N, SS/Bb_M, BB);       // (32, 32, 4)
    gemm_kernel<2,false><<<gq, 256, smem1>>>(
        (const __nv_bfloat16*)p_K, nullptr, (const __nv_bfloat16*)p_Q, nullptr,
        nullptr, p_E, SS, DD, (long)SS*DD, (long)SS*DD, (long)SS*SS);

    // 4. reciprocal column sums, 5. row sums
    colsum_kernel<<<dim3(SS/64, BB), 256>>>();
    rowsum_kernel<<<dim3(SS/64, BB), 256>>>();

    // 6. attn = rowsum * V -> hi/lo
    attn_kernel<<<(BSD/4 + 255)/256, 256>>>();

    // 7. out = tanh(attn Wl^T + bl) (split)
    gemm_kernel<3,true><<<gp, 256, smem2>>>(
        (const __nv_bfloat16*)p_ahi, (const __nv_bfloat16*)p_alo,
        (const __nv_bfloat16*)p_Wlhi, (const __nv_bfloat16*)p_Wllo,
        bl, d_out, DD, DD, 0, 0, 0);
}